// round 5
// baseline (speedup 1.0000x reference)
#include <cuda_runtime.h>

#define N_NODES 20000
#define D       512
#define BB      2048
#define DRUG    2000
#define H1      128
#define H2      64
#define EVALS_PER_B 65
#define TOTAL_EVALS (BB * EVALS_PER_B)   // 133120
#define EB      128                       // evals per block in fused kernel
#define X1_STRIDE 132

typedef unsigned long long u64;

// packed fp32x2 fma: d = a*b + d (lane-wise). PTX-only route to SASS FFMA2.
__device__ __forceinline__ void ffma2(u64& d, u64 a, u64 b) {
    asm("fma.rn.f32x2 %0, %1, %2, %0;" : "+l"(d) : "l"(a), "l"(b));
}
__device__ __forceinline__ float pairsum(u64 v) {
    float lo, hi;
    asm("mov.b64 {%0, %1}, %2;" : "=f"(lo), "=f"(hi) : "l"(v));
    return lo + hi;
}

// Scratch (device globals — no allocation allowed)
__device__ float g_Ptop[DRUG * H1];   // embed[0:2000] @ W1[0:512]
__device__ float g_Pbot[DRUG * H1];   // embed[0:2000] @ W1[512:1024]
__device__ float g_Tbot[BB  * H1];    // embed[t[b]]   @ W1[512:1024]

// ---------------------------------------------------------------------------
// Kernel 1: projection GEMMs.
// blockIdx.y = segment: 0 -> P_top, 1 -> P_bot, 2 -> T_bot (gathered via t).
// BM=32 rows, BN=128 (full), BK=32, 256 threads, 4x4 microtile per thread.
// ---------------------------------------------------------------------------
__global__ __launch_bounds__(256) void proj_kernel(const float* __restrict__ embed,
                                                   const float* __restrict__ W1,
                                                   const int* __restrict__ t) {
    const int seg  = blockIdx.y;
    const int rows = (seg == 2) ? BB : DRUG;
    const int row0 = blockIdx.x * 32;
    if (row0 >= rows) return;
    const int woff = (seg == 0) ? 0 : D;
    float* dst = (seg == 0) ? g_Ptop : (seg == 1) ? g_Pbot : g_Tbot;

    __shared__ float As[32][32];
    __shared__ float Bs[32 * 128];

    const int tid = threadIdx.x;

    const int ar = tid >> 3;            // row in tile (0..31)
    const int ac = (tid & 7) << 2;      // k offset
    const int arow = row0 + ar;
    int srow = (arow < rows) ? arow : (rows - 1);
    if (seg == 2) srow = t[srow];       // gather tail row via t index
    const float* src = embed + (long)srow * D;

    const int ty = tid >> 5;            // 0..7 -> 4 rows each
    const int tx = tid & 31;            // 0..31 -> 4 cols each

    float acc[4][4];
#pragma unroll
    for (int r = 0; r < 4; r++)
#pragma unroll
        for (int c = 0; c < 4; c++) acc[r][c] = 0.f;

    for (int k0 = 0; k0 < D; k0 += 32) {
        float4 av = *(const float4*)(src + k0 + ac);
        *(float4*)&As[ar][ac] = av;
        const float* wsrc = W1 + (long)(woff + k0) * H1;
#pragma unroll
        for (int i = 0; i < 4; i++) {
            int f4 = tid + i * 256;
            int bk = f4 >> 5;
            int bn = (f4 & 31) << 2;
            *(float4*)&Bs[bk * 128 + bn] = *(const float4*)(wsrc + bk * H1 + bn);
        }
        __syncthreads();
#pragma unroll
        for (int k = 0; k < 32; k++) {
            float4 bv = *(float4*)&Bs[k * 128 + (tx << 2)];
#pragma unroll
            for (int r = 0; r < 4; r++) {
                float a = As[ty * 4 + r][k];
                acc[r][0] += a * bv.x;
                acc[r][1] += a * bv.y;
                acc[r][2] += a * bv.z;
                acc[r][3] += a * bv.w;
            }
        }
        __syncthreads();
    }

#pragma unroll
    for (int r = 0; r < 4; r++) {
        int row = row0 + ty * 4 + r;
        if (row < rows) {
            float4 v = make_float4(acc[r][0], acc[r][1], acc[r][2], acc[r][3]);
            *(float4*)&dst[row * H1 + (tx << 2)] = v;
        }
    }
}

// ---------------------------------------------------------------------------
// Kernel 2: fused layers 1..3, 128 evals per block, 128 threads, 8x8 microtile,
// stage-2 inner product in packed f32x2 (pairs over k).
// eval e: b = e/65, s = e%65.
//   s==0           : head=P_top[h[b]],        tail=T_bot[b],          out=pos[b]
//   s in [1,32]    : head=P_top[h[b]],        tail=P_bot[ns[b][s-1]], out=neg[b][s-1]
//   s in [33,64]   : head=P_top[ns[b][s-1]],  tail=T_bot[b],          out=neg[b][s-1]
// W2 staged in smem k-pair-interleaved: W2p[(k>>1)*128 + 2c + (k&1)]
// acc2[r][c] = f32x2 (sum over even k, sum over odd k); final = lo+hi.
// ---------------------------------------------------------------------------
__global__ __launch_bounds__(128) void mlp_kernel(const float* __restrict__ b1,
                                                  const float* __restrict__ W2,
                                                  const float* __restrict__ b2,
                                                  const float* __restrict__ W3,
                                                  const float* __restrict__ b3,
                                                  const int* __restrict__ h,
                                                  const int* __restrict__ ns,
                                                  float* __restrict__ out) {
    extern __shared__ float sm[];
    float* W2p = sm;                     // 64 k-pairs * 128 floats = 8192
    float* X1  = sm + H1 * H2;           // 128 * 132 floats

    __shared__ float b1s[H1];
    __shared__ float b2s[H2];
    __shared__ float W3s[H2];
    __shared__ const float* headp[EB];
    __shared__ const float* tailp[EB];
    __shared__ int outoff[EB];

    const int tid = threadIdx.x;
    const int e0 = blockIdx.x * EB;

    // -------- pointer / output-offset setup (1 eval per thread) ------------
    {
        int e = e0 + tid;
        int b = e / EVALS_PER_B;
        int s = e - b * EVALS_PER_B;
        int hidx, ooff;
        const float* tp;
        if (s == 0) {
            hidx = h[b];
            tp = g_Tbot + b * H1;
            ooff = b;
        } else {
            int nsv = ns[b * 64 + (s - 1)];
            if (s <= 32) {
                hidx = h[b];
                tp = g_Pbot + nsv * H1;
            } else {
                hidx = nsv;
                tp = g_Tbot + b * H1;
            }
            ooff = BB + b * 64 + (s - 1);
        }
        headp[tid] = g_Ptop + hidx * H1;
        tailp[tid] = tp;
        outoff[tid] = ooff;
    }
    if (tid < H1) b1s[tid] = b1[tid];
    if (tid < H2) { b2s[tid] = b2[tid]; W3s[tid] = W3[tid]; }
    // W2 -> k-pair-interleaved smem: W2p[(k>>1)*128 + 2c + (k&1)] = W2[k][c]
#pragma unroll
    for (int i = 0; i < 16; i++) {       // 2048 float4 / 128 threads
        int f4 = tid + i * 128;
        int k  = f4 >> 4;                // W2 row (16 float4 per 64-wide row)
        int c4 = (f4 & 15) << 2;         // starting col
        float4 v = *(const float4*)&W2[k * H2 + c4];
        float* dstp = &W2p[((k >> 1) << 7) + (k & 1)];
        dstp[(c4 + 0) * 2] = v.x;
        dstp[(c4 + 1) * 2] = v.y;
        dstp[(c4 + 2) * 2] = v.z;
        dstp[(c4 + 3) * 2] = v.w;
    }
    __syncthreads();

    // -------- Stage 1: X1 [128][128] (warp-uniform eval row per iter) ------
#pragma unroll
    for (int i = 0; i < 32; i++) {
        int idx4 = tid + i * 128;        // 0..4095 float4s
        int e = idx4 >> 5;               // warp-uniform
        int c = (idx4 & 31) << 2;
        float4 hv = *(const float4*)(headp[e] + c);
        float4 tv = *(const float4*)(tailp[e] + c);
        float4 bv = *(const float4*)&b1s[c];
        float4 xv;
        xv.x = fmaxf(hv.x + tv.x + bv.x, 0.f);
        xv.y = fmaxf(hv.y + tv.y + bv.y, 0.f);
        xv.z = fmaxf(hv.z + tv.z + bv.z, 0.f);
        xv.w = fmaxf(hv.w + tv.w + bv.w, 0.f);
        *(float4*)&X1[e * X1_STRIDE + c] = xv;
    }
    __syncthreads();

    // -------- Stage 2: 8x8 microtile GEMM in packed f32x2 ------------------
    // thread (ty,tx): rows ty+16r (r<8), cols {4tx..4tx+3, 32+4tx..32+4tx+3}
    const int ty = tid >> 3;             // 0..15
    const int tx = tid & 7;              // 0..7
    u64 acc2[8][8];
#pragma unroll
    for (int r = 0; r < 8; r++)
#pragma unroll
        for (int c = 0; c < 8; c++) acc2[r][c] = 0ULL;

    for (int k0 = 0; k0 < H1; k0 += 4) {
        ulonglong2 av[8];                // .x = X1[k0,k0+1], .y = X1[k0+2,k0+3]
#pragma unroll
        for (int r = 0; r < 8; r++)
            av[r] = *(const ulonglong2*)&X1[(ty + 16 * r) * X1_STRIDE + k0];
#pragma unroll
        for (int p = 0; p < 2; p++) {    // k-pair (k0+2p, k0+2p+1)
            const float* wrow = &W2p[(((k0 >> 1) + p) << 7)];
            ulonglong2 w0 = *(const ulonglong2*)&wrow[(tx << 3)];        // cols 4tx,4tx+1
            ulonglong2 w1 = *(const ulonglong2*)&wrow[(tx << 3) + 4];    // cols 4tx+2,4tx+3
            ulonglong2 w2 = *(const ulonglong2*)&wrow[64 + (tx << 3)];   // cols 32+4tx..
            ulonglong2 w3 = *(const ulonglong2*)&wrow[64 + (tx << 3) + 4];
#pragma unroll
            for (int r = 0; r < 8; r++) {
                u64 a = p ? av[r].y : av[r].x;
                ffma2(acc2[r][0], a, w0.x);
                ffma2(acc2[r][1], a, w0.y);
                ffma2(acc2[r][2], a, w1.x);
                ffma2(acc2[r][3], a, w1.y);
                ffma2(acc2[r][4], a, w2.x);
                ffma2(acc2[r][5], a, w2.y);
                ffma2(acc2[r][6], a, w3.x);
                ffma2(acc2[r][7], a, w3.y);
            }
        }
    }

    // -------- Stage 3: out = relu(acc + b2) . W3 + b3 ----------------------
    const float b3v = b3[0];
#pragma unroll
    for (int r = 0; r < 8; r++) {
        float p = 0.f;
#pragma unroll
        for (int j = 0; j < 2; j++)
#pragma unroll
            for (int i = 0; i < 4; i++) {
                int c = j * 32 + (tx << 2) + i;
                float a = pairsum(acc2[r][j * 4 + i]);
                p += fmaxf(a + b2s[c], 0.f) * W3s[c];
            }
        p += __shfl_xor_sync(0xffffffffu, p, 4, 8);
        p += __shfl_xor_sync(0xffffffffu, p, 2, 8);
        p += __shfl_xor_sync(0xffffffffu, p, 1, 8);
        if (tx == 0) out[outoff[ty + 16 * r]] = p + b3v;
    }
}

// ---------------------------------------------------------------------------
extern "C" void kernel_launch(void* const* d_in, const int* in_sizes, int n_in,
                              void* d_out, int out_size) {
    const float* embed = (const float*)d_in[0];
    const float* W1    = (const float*)d_in[1];
    const float* b1    = (const float*)d_in[2];
    const float* W2    = (const float*)d_in[3];
    const float* b2    = (const float*)d_in[4];
    const float* W3    = (const float*)d_in[5];
    const float* b3    = (const float*)d_in[6];
    const int*   h     = (const int*)d_in[7];
    const int*   t     = (const int*)d_in[8];
    const int*   ns    = (const int*)d_in[9];
    float* out = (float*)d_out;

    // Idempotent, not a stream op (invisible to graph capture), no static guard.
    const int dyn_smem = (H1 * H2 + EB * X1_STRIDE) * (int)sizeof(float); // 100352 B
    cudaFuncSetAttribute(mlp_kernel, cudaFuncAttributeMaxDynamicSharedMemorySize, dyn_smem);

    dim3 g1(64, 3);   // 64 row-tiles x 3 segments (extras early-exit)
    proj_kernel<<<g1, 256>>>(embed, W1, t);

    mlp_kernel<<<TOTAL_EVALS / EB, 128, dyn_smem>>>(b1, W2, b2, W3, b3, h, ns, out);
}

// round 10
// speedup vs baseline: 1.0995x; 1.0995x over previous
#include <cuda_runtime.h>

#define N_NODES 20000
#define D       512
#define BB      2048
#define DRUG    2000
#define H1      128
#define H2      64
#define EVALS_PER_B 65
#define TOTAL_EVALS (BB * EVALS_PER_B)   // 133120
#define EB      128                       // evals per block in fused kernel
#define X1_STRIDE 132

typedef unsigned long long u64;

// packed fp32x2 fma: d = a*b + d (lane-wise). PTX-only route to SASS FFMA2.
__device__ __forceinline__ void ffma2(u64& d, u64 a, u64 b) {
    asm("fma.rn.f32x2 %0, %1, %2, %0;" : "+l"(d) : "l"(a), "l"(b));
}
__device__ __forceinline__ float pairsum(u64 v) {
    float lo, hi;
    asm("mov.b64 {%0, %1}, %2;" : "=f"(lo), "=f"(hi) : "l"(v));
    return lo + hi;
}

// Scratch (device globals — no allocation allowed)
__device__ float g_Ptop[DRUG * H1];   // embed[0:2000] @ W1[0:512]
__device__ float g_Pbot[DRUG * H1];   // embed[0:2000] @ W1[512:1024]
__device__ float g_Tbot[BB  * H1];    // embed[t[b]]   @ W1[512:1024]

// ---------------------------------------------------------------------------
// Kernel 1: projection GEMMs.
// blockIdx.y = segment: 0 -> P_top, 1 -> P_bot, 2 -> T_bot (gathered via t).
// BM=16 rows (wave-balance: 381 blocks vs 190), BN=128, BK=32, 256 threads,
// 2x4 microtile per thread.
// ---------------------------------------------------------------------------
__global__ __launch_bounds__(256) void proj_kernel(const float* __restrict__ embed,
                                                   const float* __restrict__ W1,
                                                   const int* __restrict__ t) {
    const int seg  = blockIdx.y;
    const int rows = (seg == 2) ? BB : DRUG;
    const int row0 = blockIdx.x * 16;
    if (row0 >= rows) return;
    const int woff = (seg == 0) ? 0 : D;
    float* dst = (seg == 0) ? g_Ptop : (seg == 1) ? g_Pbot : g_Tbot;

    __shared__ float As[16][32];
    __shared__ float Bs[32 * 128];

    const int tid = threadIdx.x;

    // A-tile load mapping: threads 0..127 load one float4 per k-chunk
    const int ar = tid >> 3;            // row in tile (0..15 for tid<128)
    const int ac = (tid & 7) << 2;      // k offset
    const int arow = row0 + (ar & 15);
    int srow = (arow < rows) ? arow : (rows - 1);
    if (seg == 2) srow = t[srow];       // gather tail row via t index
    const float* src = embed + (long)srow * D;

    const int ty = tid >> 5;            // warp id 0..7 -> rows 2ty, 2ty+1
    const int tx = tid & 31;            // 0..31 -> 4 cols each

    float acc[2][4];
#pragma unroll
    for (int r = 0; r < 2; r++)
#pragma unroll
        for (int c = 0; c < 4; c++) acc[r][c] = 0.f;

    for (int k0 = 0; k0 < D; k0 += 32) {
        if (tid < 128) {
            float4 av = *(const float4*)(src + k0 + ac);
            *(float4*)&As[ar][ac] = av;
        }
        const float* wsrc = W1 + (long)(woff + k0) * H1;
#pragma unroll
        for (int i = 0; i < 4; i++) {
            int f4 = tid + i * 256;
            int bk = f4 >> 5;
            int bn = (f4 & 31) << 2;
            *(float4*)&Bs[bk * 128 + bn] = *(const float4*)(wsrc + bk * H1 + bn);
        }
        __syncthreads();
#pragma unroll
        for (int k = 0; k < 32; k++) {
            float4 bv = *(float4*)&Bs[k * 128 + (tx << 2)];
#pragma unroll
            for (int r = 0; r < 2; r++) {
                float a = As[ty * 2 + r][k];   // warp-uniform row -> broadcast
                acc[r][0] += a * bv.x;
                acc[r][1] += a * bv.y;
                acc[r][2] += a * bv.z;
                acc[r][3] += a * bv.w;
            }
        }
        __syncthreads();
    }

#pragma unroll
    for (int r = 0; r < 2; r++) {
        int row = row0 + ty * 2 + r;
        if (row < rows) {
            float4 v = make_float4(acc[r][0], acc[r][1], acc[r][2], acc[r][3]);
            *(float4*)&dst[row * H1 + (tx << 2)] = v;
        }
    }
}

// ---------------------------------------------------------------------------
// Kernel 2: fused layers 1..3. 128 evals/block, 256 threads, 4x8 microtile.
// thread (ty=tid>>3 in [0,32), tx=tid&7): rows ty+32r (r<4),
// cols c(g,i) = 16g + 2tx + i  (g<4, i<2)  -> conflict-free W2p LDS.128.
// W2p k-pair-interleaved: W2p[(k>>1)*128 + 2c + (k&1)] = W2[k][c].
// acc2[r][2g+i] = f32x2 accum over (even k, odd k) for col c(g,i); final lo+hi.
// ---------------------------------------------------------------------------
__global__ __launch_bounds__(256, 2) void mlp_kernel(const float* __restrict__ b1,
                                                     const float* __restrict__ W2,
                                                     const float* __restrict__ b2,
                                                     const float* __restrict__ W3,
                                                     const float* __restrict__ b3,
                                                     const int* __restrict__ h,
                                                     const int* __restrict__ ns,
                                                     float* __restrict__ out) {
    extern __shared__ float sm[];
    float* W2p = sm;                     // 64 k-pairs * 128 floats = 8192
    float* X1  = sm + H1 * H2;           // 128 * 132 floats

    __shared__ float b1s[H1];
    __shared__ float b2s[H2];
    __shared__ float W3s[H2];
    __shared__ const float* headp[EB];
    __shared__ const float* tailp[EB];
    __shared__ int outoff[EB];

    const int tid = threadIdx.x;
    const int e0 = blockIdx.x * EB;

    // -------- pointer / output-offset setup (first 128 threads) ------------
    if (tid < EB) {
        int e = e0 + tid;
        int b = e / EVALS_PER_B;
        int s = e - b * EVALS_PER_B;
        int hidx, ooff;
        const float* tp;
        if (s == 0) {
            hidx = h[b];
            tp = g_Tbot + b * H1;
            ooff = b;
        } else {
            int nsv = ns[b * 64 + (s - 1)];
            if (s <= 32) {
                hidx = h[b];
                tp = g_Pbot + nsv * H1;
            } else {
                hidx = nsv;
                tp = g_Tbot + b * H1;
            }
            ooff = BB + b * 64 + (s - 1);
        }
        headp[tid] = g_Ptop + hidx * H1;
        tailp[tid] = tp;
        outoff[tid] = ooff;
    }
    if (tid < H1) b1s[tid] = b1[tid];
    if (tid >= 128 && tid < 128 + H2) b2s[tid - 128] = b2[tid - 128];
    if (tid >= 192 && tid < 192 + H2) W3s[tid - 192] = W3[tid - 192];
    // W2 -> k-pair-interleaved smem
#pragma unroll
    for (int i = 0; i < 8; i++) {        // 2048 float4 / 256 threads
        int f4 = tid + i * 256;
        int k  = f4 >> 4;                // W2 row (16 float4 per 64-wide row)
        int c4 = (f4 & 15) << 2;         // starting col
        float4 v = *(const float4*)&W2[k * H2 + c4];
        float* dstp = &W2p[((k >> 1) << 7) + (k & 1)];
        dstp[(c4 + 0) * 2] = v.x;
        dstp[(c4 + 1) * 2] = v.y;
        dstp[(c4 + 2) * 2] = v.z;
        dstp[(c4 + 3) * 2] = v.w;
    }
    __syncthreads();

    // -------- Stage 1: X1 [128][128] (warp-uniform eval row per iter) ------
#pragma unroll
    for (int i = 0; i < 16; i++) {
        int idx4 = tid + i * 256;        // 0..4095 float4s
        int e = idx4 >> 5;               // warp-uniform
        int c = (idx4 & 31) << 2;
        float4 hv = *(const float4*)(headp[e] + c);
        float4 tv = *(const float4*)(tailp[e] + c);
        float4 bv = *(const float4*)&b1s[c];
        float4 xv;
        xv.x = fmaxf(hv.x + tv.x + bv.x, 0.f);
        xv.y = fmaxf(hv.y + tv.y + bv.y, 0.f);
        xv.z = fmaxf(hv.z + tv.z + bv.z, 0.f);
        xv.w = fmaxf(hv.w + tv.w + bv.w, 0.f);
        *(float4*)&X1[e * X1_STRIDE + c] = xv;
    }
    __syncthreads();

    // -------- Stage 2: 4x8 microtile GEMM in packed f32x2 ------------------
    const int ty = tid >> 3;             // 0..31, rows ty + 32r
    const int tx = tid & 7;              // 0..7
    u64 acc2[4][8];
#pragma unroll
    for (int r = 0; r < 4; r++)
#pragma unroll
        for (int c = 0; c < 8; c++) acc2[r][c] = 0ULL;

    for (int k0 = 0; k0 < H1; k0 += 4) {
        ulonglong2 av[4];                // .x = X1[k0,k0+1], .y = X1[k0+2,k0+3]
#pragma unroll
        for (int r = 0; r < 4; r++)
            av[r] = *(const ulonglong2*)&X1[(ty + 32 * r) * X1_STRIDE + k0];
#pragma unroll
        for (int p = 0; p < 2; p++) {    // k-pair (k0+2p, k0+2p+1)
            const float* wrow = &W2p[(((k0 >> 1) + p) << 7)];
            ulonglong2 wv[4];
#pragma unroll
            for (int g = 0; g < 4; g++)  // cols {16g+2tx, 16g+2tx+1}
                wv[g] = *(const ulonglong2*)&wrow[32 * g + (tx << 2)];
#pragma unroll
            for (int r = 0; r < 4; r++) {
                u64 a = p ? av[r].y : av[r].x;
#pragma unroll
                for (int g = 0; g < 4; g++) {
                    ffma2(acc2[r][2 * g + 0], a, wv[g].x);
                    ffma2(acc2[r][2 * g + 1], a, wv[g].y);
                }
            }
        }
    }

    // -------- Stage 3: out = relu(acc + b2) . W3 + b3 ----------------------
    const float b3v = b3[0];
#pragma unroll
    for (int r = 0; r < 4; r++) {
        float p = 0.f;
#pragma unroll
        for (int g = 0; g < 4; g++)
#pragma unroll
            for (int i = 0; i < 2; i++) {
                int c = 16 * g + 2 * tx + i;
                float a = pairsum(acc2[r][2 * g + i]);
                p += fmaxf(a + b2s[c], 0.f) * W3s[c];
            }
        p += __shfl_xor_sync(0xffffffffu, p, 4, 8);
        p += __shfl_xor_sync(0xffffffffu, p, 2, 8);
        p += __shfl_xor_sync(0xffffffffu, p, 1, 8);
        if (tx == 0) out[outoff[ty + 32 * r]] = p + b3v;
    }
}

// ---------------------------------------------------------------------------
extern "C" void kernel_launch(void* const* d_in, const int* in_sizes, int n_in,
                              void* d_out, int out_size) {
    const float* embed = (const float*)d_in[0];
    const float* W1    = (const float*)d_in[1];
    const float* b1    = (const float*)d_in[2];
    const float* W2    = (const float*)d_in[3];
    const float* b2    = (const float*)d_in[4];
    const float* W3    = (const float*)d_in[5];
    const float* b3    = (const float*)d_in[6];
    const int*   h     = (const int*)d_in[7];
    const int*   t     = (const int*)d_in[8];
    const int*   ns    = (const int*)d_in[9];
    float* out = (float*)d_out;

    // Idempotent, not a stream op (invisible to graph capture), no static guard.
    const int dyn_smem = (H1 * H2 + EB * X1_STRIDE) * (int)sizeof(float); // 100352 B
    cudaFuncSetAttribute(mlp_kernel, cudaFuncAttributeMaxDynamicSharedMemorySize, dyn_smem);

    dim3 g1(128, 3);  // 128 row-tiles (BM=16) x 3 segments (extras early-exit)
    proj_kernel<<<g1, 256>>>(embed, W1, t);

    mlp_kernel<<<TOTAL_EVALS / EB, 256, dyn_smem>>>(b1, W2, b2, W3, b3, h, ns, out);
}

// round 11
// speedup vs baseline: 1.1694x; 1.0635x over previous
#include <cuda_runtime.h>

#define N_NODES 20000
#define D       512
#define BB      2048
#define DRUG    2000
#define H1      128
#define H2      64
#define EVALS_PER_B 65
#define TOTAL_EVALS (BB * EVALS_PER_B)   // 133120
#define EB      128                       // evals per block in fused kernel
#define X1_STRIDE 132

typedef unsigned long long u64;

// packed fp32x2 fma: d = a*b + d (lane-wise). PTX-only route to SASS FFMA2.
__device__ __forceinline__ void ffma2(u64& d, u64 a, u64 b) {
    asm("fma.rn.f32x2 %0, %1, %2, %0;" : "+l"(d) : "l"(a), "l"(b));
}
__device__ __forceinline__ float pairsum(u64 v) {
    float lo, hi;
    asm("mov.b64 {%0, %1}, %2;" : "=f"(lo), "=f"(hi) : "l"(v));
    return lo + hi;
}

// Scratch (device globals — no allocation allowed)
__device__ float g_Ptop[DRUG * H1];   // embed[0:2000] @ W1[0:512]
__device__ float g_Pbot[DRUG * H1];   // embed[0:2000] @ W1[512:1024]
__device__ float g_Tbot[BB  * H1];    // embed[t[b]]   @ W1[512:1024]

// ---------------------------------------------------------------------------
// Kernel 1: projection GEMMs — REVERTED to round-5 BM=32 config (measured-good).
// blockIdx.y = segment: 0 -> P_top, 1 -> P_bot, 2 -> T_bot (gathered via t).
// BM=32 rows, BN=128, BK=32, 256 threads, 4x4 microtile per thread.
// ---------------------------------------------------------------------------
__global__ __launch_bounds__(256) void proj_kernel(const float* __restrict__ embed,
                                                   const float* __restrict__ W1,
                                                   const int* __restrict__ t) {
    const int seg  = blockIdx.y;
    const int rows = (seg == 2) ? BB : DRUG;
    const int row0 = blockIdx.x * 32;
    if (row0 >= rows) return;
    const int woff = (seg == 0) ? 0 : D;
    float* dst = (seg == 0) ? g_Ptop : (seg == 1) ? g_Pbot : g_Tbot;

    __shared__ float As[32][32];
    __shared__ float Bs[32 * 128];

    const int tid = threadIdx.x;

    const int ar = tid >> 3;            // row in tile (0..31)
    const int ac = (tid & 7) << 2;      // k offset
    const int arow = row0 + ar;
    int srow = (arow < rows) ? arow : (rows - 1);
    if (seg == 2) srow = t[srow];       // gather tail row via t index
    const float* src = embed + (long)srow * D;

    const int ty = tid >> 5;            // 0..7 -> 4 rows each
    const int tx = tid & 31;            // 0..31 -> 4 cols each

    float acc[4][4];
#pragma unroll
    for (int r = 0; r < 4; r++)
#pragma unroll
        for (int c = 0; c < 4; c++) acc[r][c] = 0.f;

    for (int k0 = 0; k0 < D; k0 += 32) {
        float4 av = *(const float4*)(src + k0 + ac);
        *(float4*)&As[ar][ac] = av;
        const float* wsrc = W1 + (long)(woff + k0) * H1;
#pragma unroll
        for (int i = 0; i < 4; i++) {
            int f4 = tid + i * 256;
            int bk = f4 >> 5;
            int bn = (f4 & 31) << 2;
            *(float4*)&Bs[bk * 128 + bn] = *(const float4*)(wsrc + bk * H1 + bn);
        }
        __syncthreads();
#pragma unroll
        for (int k = 0; k < 32; k++) {
            float4 bv = *(float4*)&Bs[k * 128 + (tx << 2)];
#pragma unroll
            for (int r = 0; r < 4; r++) {
                float a = As[ty * 4 + r][k];   // warp-uniform row -> broadcast
                acc[r][0] += a * bv.x;
                acc[r][1] += a * bv.y;
                acc[r][2] += a * bv.z;
                acc[r][3] += a * bv.w;
            }
        }
        __syncthreads();
    }

#pragma unroll
    for (int r = 0; r < 4; r++) {
        int row = row0 + ty * 4 + r;
        if (row < rows) {
            float4 v = make_float4(acc[r][0], acc[r][1], acc[r][2], acc[r][3]);
            *(float4*)&dst[row * H1 + (tx << 2)] = v;
        }
    }
}

// ---------------------------------------------------------------------------
// Kernel 2: fused layers 1..3. 128 evals/block, 256 threads, 4x8 microtile.
// (unchanged from round 10: measured 63.1 us, occ 23.2%, L1-bound at 72%)
// thread (ty=tid>>3 in [0,32), tx=tid&7): rows ty+32r (r<4),
// cols c(g,i) = 16g + 2tx + i  (g<4, i<2)  -> conflict-free W2p LDS.128.
// W2p k-pair-interleaved: W2p[(k>>1)*128 + 2c + (k&1)] = W2[k][c].
// acc2[r][2g+i] = f32x2 accum over (even k, odd k) for col c(g,i); final lo+hi.
// ---------------------------------------------------------------------------
__global__ __launch_bounds__(256, 2) void mlp_kernel(const float* __restrict__ b1,
                                                     const float* __restrict__ W2,
                                                     const float* __restrict__ b2,
                                                     const float* __restrict__ W3,
                                                     const float* __restrict__ b3,
                                                     const int* __restrict__ h,
                                                     const int* __restrict__ ns,
                                                     float* __restrict__ out) {
    extern __shared__ float sm[];
    float* W2p = sm;                     // 64 k-pairs * 128 floats = 8192
    float* X1  = sm + H1 * H2;           // 128 * 132 floats

    __shared__ float b1s[H1];
    __shared__ float b2s[H2];
    __shared__ float W3s[H2];
    __shared__ const float* headp[EB];
    __shared__ const float* tailp[EB];
    __shared__ int outoff[EB];

    const int tid = threadIdx.x;
    const int e0 = blockIdx.x * EB;

    // -------- pointer / output-offset setup (first 128 threads) ------------
    if (tid < EB) {
        int e = e0 + tid;
        int b = e / EVALS_PER_B;
        int s = e - b * EVALS_PER_B;
        int hidx, ooff;
        const float* tp;
        if (s == 0) {
            hidx = h[b];
            tp = g_Tbot + b * H1;
            ooff = b;
        } else {
            int nsv = ns[b * 64 + (s - 1)];
            if (s <= 32) {
                hidx = h[b];
                tp = g_Pbot + nsv * H1;
            } else {
                hidx = nsv;
                tp = g_Tbot + b * H1;
            }
            ooff = BB + b * 64 + (s - 1);
        }
        headp[tid] = g_Ptop + hidx * H1;
        tailp[tid] = tp;
        outoff[tid] = ooff;
    }
    if (tid < H1) b1s[tid] = b1[tid];
    if (tid >= 128 && tid < 128 + H2) b2s[tid - 128] = b2[tid - 128];
    if (tid >= 192 && tid < 192 + H2) W3s[tid - 192] = W3[tid - 192];
    // W2 -> k-pair-interleaved smem
#pragma unroll
    for (int i = 0; i < 8; i++) {        // 2048 float4 / 256 threads
        int f4 = tid + i * 256;
        int k  = f4 >> 4;                // W2 row (16 float4 per 64-wide row)
        int c4 = (f4 & 15) << 2;         // starting col
        float4 v = *(const float4*)&W2[k * H2 + c4];
        float* dstp = &W2p[((k >> 1) << 7) + (k & 1)];
        dstp[(c4 + 0) * 2] = v.x;
        dstp[(c4 + 1) * 2] = v.y;
        dstp[(c4 + 2) * 2] = v.z;
        dstp[(c4 + 3) * 2] = v.w;
    }
    __syncthreads();

    // -------- Stage 1: X1 [128][128] (warp-uniform eval row per iter) ------
#pragma unroll
    for (int i = 0; i < 16; i++) {
        int idx4 = tid + i * 256;        // 0..4095 float4s
        int e = idx4 >> 5;               // warp-uniform
        int c = (idx4 & 31) << 2;
        float4 hv = *(const float4*)(headp[e] + c);
        float4 tv = *(const float4*)(tailp[e] + c);
        float4 bv = *(const float4*)&b1s[c];
        float4 xv;
        xv.x = fmaxf(hv.x + tv.x + bv.x, 0.f);
        xv.y = fmaxf(hv.y + tv.y + bv.y, 0.f);
        xv.z = fmaxf(hv.z + tv.z + bv.z, 0.f);
        xv.w = fmaxf(hv.w + tv.w + bv.w, 0.f);
        *(float4*)&X1[e * X1_STRIDE + c] = xv;
    }
    __syncthreads();

    // -------- Stage 2: 4x8 microtile GEMM in packed f32x2 ------------------
    const int ty = tid >> 3;             // 0..31, rows ty + 32r
    const int tx = tid & 7;              // 0..7
    u64 acc2[4][8];
#pragma unroll
    for (int r = 0; r < 4; r++)
#pragma unroll
        for (int c = 0; c < 8; c++) acc2[r][c] = 0ULL;

    for (int k0 = 0; k0 < H1; k0 += 4) {
        ulonglong2 av[4];                // .x = X1[k0,k0+1], .y = X1[k0+2,k0+3]
#pragma unroll
        for (int r = 0; r < 4; r++)
            av[r] = *(const ulonglong2*)&X1[(ty + 32 * r) * X1_STRIDE + k0];
#pragma unroll
        for (int p = 0; p < 2; p++) {    // k-pair (k0+2p, k0+2p+1)
            const float* wrow = &W2p[(((k0 >> 1) + p) << 7)];
            ulonglong2 wv[4];
#pragma unroll
            for (int g = 0; g < 4; g++)  // cols {16g+2tx, 16g+2tx+1}
                wv[g] = *(const ulonglong2*)&wrow[32 * g + (tx << 2)];
#pragma unroll
            for (int r = 0; r < 4; r++) {
                u64 a = p ? av[r].y : av[r].x;
#pragma unroll
                for (int g = 0; g < 4; g++) {
                    ffma2(acc2[r][2 * g + 0], a, wv[g].x);
                    ffma2(acc2[r][2 * g + 1], a, wv[g].y);
                }
            }
        }
    }

    // -------- Stage 3: out = relu(acc + b2) . W3 + b3 ----------------------
    const float b3v = b3[0];
#pragma unroll
    for (int r = 0; r < 4; r++) {
        float p = 0.f;
#pragma unroll
        for (int g = 0; g < 4; g++)
#pragma unroll
            for (int i = 0; i < 2; i++) {
                int c = 16 * g + 2 * tx + i;
                float a = pairsum(acc2[r][2 * g + i]);
                p += fmaxf(a + b2s[c], 0.f) * W3s[c];
            }
        p += __shfl_xor_sync(0xffffffffu, p, 4, 8);
        p += __shfl_xor_sync(0xffffffffu, p, 2, 8);
        p += __shfl_xor_sync(0xffffffffu, p, 1, 8);
        if (tx == 0) out[outoff[ty + 32 * r]] = p + b3v;
    }
}

// ---------------------------------------------------------------------------
extern "C" void kernel_launch(void* const* d_in, const int* in_sizes, int n_in,
                              void* d_out, int out_size) {
    const float* embed = (const float*)d_in[0];
    const float* W1    = (const float*)d_in[1];
    const float* b1    = (const float*)d_in[2];
    const float* W2    = (const float*)d_in[3];
    const float* b2    = (const float*)d_in[4];
    const float* W3    = (const float*)d_in[5];
    const float* b3    = (const float*)d_in[6];
    const int*   h     = (const int*)d_in[7];
    const int*   t     = (const int*)d_in[8];
    const int*   ns    = (const int*)d_in[9];
    float* out = (float*)d_out;

    // Idempotent, not a stream op (invisible to graph capture), no static guard.
    const int dyn_smem = (H1 * H2 + EB * X1_STRIDE) * (int)sizeof(float); // 100352 B
    cudaFuncSetAttribute(mlp_kernel, cudaFuncAttributeMaxDynamicSharedMemorySize, dyn_smem);

    dim3 g1(64, 3);   // 64 row-tiles (BM=32) x 3 segments (extras early-exit)
    proj_kernel<<<g1, 256>>>(embed, W1, t);

    mlp_kernel<<<TOTAL_EVALS / EB, 256, dyn_smem>>>(b1, W2, b2, W3, b3, h, ns, out);
}

// round 12
// speedup vs baseline: 1.2198x; 1.0431x over previous
#include <cuda_runtime.h>

#define N_NODES 20000
#define D       512
#define BB      2048
#define DRUG    2000
#define H1      128
#define H2      64
#define EVALS_PER_B 65
#define TOTAL_EVALS (BB * EVALS_PER_B)   // 133120
#define EB      128                       // evals per block in fused kernel
#define X1_STRIDE 132
#define PART    (2048 * H1)               // offset of k-partial #1 in each scratch array

typedef unsigned long long u64;

// packed fp32x2 fma: d = a*b + d (lane-wise). PTX-only route to SASS FFMA2.
__device__ __forceinline__ void ffma2(u64& d, u64 a, u64 b) {
    asm("fma.rn.f32x2 %0, %1, %2, %0;" : "+l"(d) : "l"(a), "l"(b));
}
__device__ __forceinline__ float pairsum(u64 v) {
    float lo, hi;
    asm("mov.b64 {%0, %1}, %2;" : "=f"(lo), "=f"(hi) : "l"(v));
    return lo + hi;
}

// Scratch (device globals — no allocation allowed). Each array holds two
// k-partials at uniform stride PART (rows padded to 2048 for Ptop/Pbot).
__device__ float g_Ptop[2 * PART];   // embed[0:2000] @ W1[kz][0:512-half, :128top]
__device__ float g_Pbot[2 * PART];
__device__ float g_Tbot[2 * PART];

// ---------------------------------------------------------------------------
// Kernel 1: projection GEMMs, split-K=2.
// grid (64, 3, 2): blockIdx.y = segment (0 Ptop, 1 Pbot, 2 Tbot via t-gather),
// blockIdx.z = k-half. BM=32, BN=128, BK=32, 256 threads, 4x4 microtile.
// Tile shape (and smem reuse ratio) identical to the measured-good round-5
// config; only the k-extent halves -> 380 half-cost blocks vs 190 (wave fill).
// ---------------------------------------------------------------------------
__global__ __launch_bounds__(256) void proj_kernel(const float* __restrict__ embed,
                                                   const float* __restrict__ W1,
                                                   const int* __restrict__ t) {
    const int seg  = blockIdx.y;
    const int kz   = blockIdx.z;
    const int rows = (seg == 2) ? BB : DRUG;
    const int row0 = blockIdx.x * 32;
    if (row0 >= rows) return;
    const int woff = (seg == 0) ? 0 : D;
    float* dst = ((seg == 0) ? g_Ptop : (seg == 1) ? g_Pbot : g_Tbot) + kz * PART;

    __shared__ float As[32][32];
    __shared__ float Bs[32 * 128];

    const int tid = threadIdx.x;

    const int ar = tid >> 3;            // row in tile (0..31)
    const int ac = (tid & 7) << 2;      // k offset
    const int arow = row0 + ar;
    int srow = (arow < rows) ? arow : (rows - 1);
    if (seg == 2) srow = t[srow];       // gather tail row via t index
    const float* src = embed + (long)srow * D;

    const int ty = tid >> 5;            // 0..7 -> 4 rows each
    const int tx = tid & 31;            // 0..31 -> 4 cols each

    float acc[4][4];
#pragma unroll
    for (int r = 0; r < 4; r++)
#pragma unroll
        for (int c = 0; c < 4; c++) acc[r][c] = 0.f;

    const int kbeg = kz * 256;
    for (int k0 = kbeg; k0 < kbeg + 256; k0 += 32) {
        float4 av = *(const float4*)(src + k0 + ac);
        *(float4*)&As[ar][ac] = av;
        const float* wsrc = W1 + (long)(woff + k0) * H1;
#pragma unroll
        for (int i = 0; i < 4; i++) {
            int f4 = tid + i * 256;
            int bk = f4 >> 5;
            int bn = (f4 & 31) << 2;
            *(float4*)&Bs[bk * 128 + bn] = *(const float4*)(wsrc + bk * H1 + bn);
        }
        __syncthreads();
#pragma unroll
        for (int k = 0; k < 32; k++) {
            float4 bv = *(float4*)&Bs[k * 128 + (tx << 2)];
#pragma unroll
            for (int r = 0; r < 4; r++) {
                float a = As[ty * 4 + r][k];   // warp-uniform row -> broadcast
                acc[r][0] += a * bv.x;
                acc[r][1] += a * bv.y;
                acc[r][2] += a * bv.z;
                acc[r][3] += a * bv.w;
            }
        }
        __syncthreads();
    }

#pragma unroll
    for (int r = 0; r < 4; r++) {
        int row = row0 + ty * 4 + r;
        if (row < rows) {
            float4 v = make_float4(acc[r][0], acc[r][1], acc[r][2], acc[r][3]);
            *(float4*)&dst[row * H1 + (tx << 2)] = v;
        }
    }
}

// ---------------------------------------------------------------------------
// Kernel 2: fused layers 1..3. 128 evals/block, 256 threads, 4x8 microtile.
// Stage 1 now sums both k-partials: X1 = relu(head0+head1+tail0+tail1+b1),
// where partial1 lives at +PART in the same scratch array (uniform offset).
// Stages 2/3 unchanged from the measured 63.1us version.
// ---------------------------------------------------------------------------
__global__ __launch_bounds__(256, 2) void mlp_kernel(const float* __restrict__ b1,
                                                     const float* __restrict__ W2,
                                                     const float* __restrict__ b2,
                                                     const float* __restrict__ W3,
                                                     const float* __restrict__ b3,
                                                     const int* __restrict__ h,
                                                     const int* __restrict__ ns,
                                                     float* __restrict__ out) {
    extern __shared__ float sm[];
    float* W2p = sm;                     // 64 k-pairs * 128 floats = 8192
    float* X1  = sm + H1 * H2;           // 128 * 132 floats

    __shared__ float b1s[H1];
    __shared__ float b2s[H2];
    __shared__ float W3s[H2];
    __shared__ const float* headp[EB];
    __shared__ const float* tailp[EB];
    __shared__ int outoff[EB];

    const int tid = threadIdx.x;
    const int e0 = blockIdx.x * EB;

    // -------- pointer / output-offset setup (first 128 threads) ------------
    if (tid < EB) {
        int e = e0 + tid;
        int b = e / EVALS_PER_B;
        int s = e - b * EVALS_PER_B;
        int hidx, ooff;
        const float* tp;
        if (s == 0) {
            hidx = h[b];
            tp = g_Tbot + b * H1;
            ooff = b;
        } else {
            int nsv = ns[b * 64 + (s - 1)];
            if (s <= 32) {
                hidx = h[b];
                tp = g_Pbot + nsv * H1;
            } else {
                hidx = nsv;
                tp = g_Tbot + b * H1;
            }
            ooff = BB + b * 64 + (s - 1);
        }
        headp[tid] = g_Ptop + hidx * H1;
        tailp[tid] = tp;
        outoff[tid] = ooff;
    }
    if (tid < H1) b1s[tid] = b1[tid];
    if (tid >= 128 && tid < 128 + H2) b2s[tid - 128] = b2[tid - 128];
    if (tid >= 192 && tid < 192 + H2) W3s[tid - 192] = W3[tid - 192];
    // W2 -> k-pair-interleaved smem
#pragma unroll
    for (int i = 0; i < 8; i++) {        // 2048 float4 / 256 threads
        int f4 = tid + i * 256;
        int k  = f4 >> 4;                // W2 row (16 float4 per 64-wide row)
        int c4 = (f4 & 15) << 2;         // starting col
        float4 v = *(const float4*)&W2[k * H2 + c4];
        float* dstp = &W2p[((k >> 1) << 7) + (k & 1)];
        dstp[(c4 + 0) * 2] = v.x;
        dstp[(c4 + 1) * 2] = v.y;
        dstp[(c4 + 2) * 2] = v.z;
        dstp[(c4 + 3) * 2] = v.w;
    }
    __syncthreads();

    // -------- Stage 1: X1 [128][128], summing both k-partials ---------------
#pragma unroll
    for (int i = 0; i < 16; i++) {
        int idx4 = tid + i * 256;        // 0..4095 float4s
        int e = idx4 >> 5;               // warp-uniform
        int c = (idx4 & 31) << 2;
        const float* hp = headp[e] + c;
        const float* tp = tailp[e] + c;
        float4 h0 = *(const float4*)hp;
        float4 h1 = *(const float4*)(hp + PART);
        float4 t0 = *(const float4*)tp;
        float4 t1 = *(const float4*)(tp + PART);
        float4 bv = *(const float4*)&b1s[c];
        float4 xv;
        xv.x = fmaxf(h0.x + h1.x + t0.x + t1.x + bv.x, 0.f);
        xv.y = fmaxf(h0.y + h1.y + t0.y + t1.y + bv.y, 0.f);
        xv.z = fmaxf(h0.z + h1.z + t0.z + t1.z + bv.z, 0.f);
        xv.w = fmaxf(h0.w + h1.w + t0.w + t1.w + bv.w, 0.f);
        *(float4*)&X1[e * X1_STRIDE + c] = xv;
    }
    __syncthreads();

    // -------- Stage 2: 4x8 microtile GEMM in packed f32x2 ------------------
    const int ty = tid >> 3;             // 0..31, rows ty + 32r
    const int tx = tid & 7;              // 0..7
    u64 acc2[4][8];
#pragma unroll
    for (int r = 0; r < 4; r++)
#pragma unroll
        for (int c = 0; c < 8; c++) acc2[r][c] = 0ULL;

    for (int k0 = 0; k0 < H1; k0 += 4) {
        ulonglong2 av[4];                // .x = X1[k0,k0+1], .y = X1[k0+2,k0+3]
#pragma unroll
        for (int r = 0; r < 4; r++)
            av[r] = *(const ulonglong2*)&X1[(ty + 32 * r) * X1_STRIDE + k0];
#pragma unroll
        for (int p = 0; p < 2; p++) {    // k-pair (k0+2p, k0+2p+1)
            const float* wrow = &W2p[(((k0 >> 1) + p) << 7)];
            ulonglong2 wv[4];
#pragma unroll
            for (int g = 0; g < 4; g++)  // cols {16g+2tx, 16g+2tx+1}
                wv[g] = *(const ulonglong2*)&wrow[32 * g + (tx << 2)];
#pragma unroll
            for (int r = 0; r < 4; r++) {
                u64 a = p ? av[r].y : av[r].x;
#pragma unroll
                for (int g = 0; g < 4; g++) {
                    ffma2(acc2[r][2 * g + 0], a, wv[g].x);
                    ffma2(acc2[r][2 * g + 1], a, wv[g].y);
                }
            }
        }
    }

    // -------- Stage 3: out = relu(acc + b2) . W3 + b3 ----------------------
    const float b3v = b3[0];
#pragma unroll
    for (int r = 0; r < 4; r++) {
        float p = 0.f;
#pragma unroll
        for (int g = 0; g < 4; g++)
#pragma unroll
            for (int i = 0; i < 2; i++) {
                int c = 16 * g + 2 * tx + i;
                float a = pairsum(acc2[r][2 * g + i]);
                p += fmaxf(a + b2s[c], 0.f) * W3s[c];
            }
        p += __shfl_xor_sync(0xffffffffu, p, 4, 8);
        p += __shfl_xor_sync(0xffffffffu, p, 2, 8);
        p += __shfl_xor_sync(0xffffffffu, p, 1, 8);
        if (tx == 0) out[outoff[ty + 32 * r]] = p + b3v;
    }
}

// ---------------------------------------------------------------------------
extern "C" void kernel_launch(void* const* d_in, const int* in_sizes, int n_in,
                              void* d_out, int out_size) {
    const float* embed = (const float*)d_in[0];
    const float* W1    = (const float*)d_in[1];
    const float* b1    = (const float*)d_in[2];
    const float* W2    = (const float*)d_in[3];
    const float* b2    = (const float*)d_in[4];
    const float* W3    = (const float*)d_in[5];
    const float* b3    = (const float*)d_in[6];
    const int*   h     = (const int*)d_in[7];
    const int*   t     = (const int*)d_in[8];
    const int*   ns    = (const int*)d_in[9];
    float* out = (float*)d_out;

    // Idempotent, not a stream op (invisible to graph capture), no static guard.
    const int dyn_smem = (H1 * H2 + EB * X1_STRIDE) * (int)sizeof(float); // 100352 B
    cudaFuncSetAttribute(mlp_kernel, cudaFuncAttributeMaxDynamicSharedMemorySize, dyn_smem);

    dim3 g1(64, 3, 2);  // 64 row-tiles x 3 segments x 2 k-halves
    proj_kernel<<<g1, 256>>>(embed, W1, t);

    mlp_kernel<<<TOTAL_EVALS / EB, 256, dyn_smem>>>(b1, W2, b2, W3, b3, h, ns, out);
}

// round 17
// speedup vs baseline: 1.2482x; 1.0233x over previous
#include <cuda_runtime.h>

#define N_NODES 20000
#define D       512
#define BB      2048
#define DRUG    2000
#define H1      128
#define H2      64
#define EVALS_PER_B 65
#define TOTAL_EVALS (BB * EVALS_PER_B)   // 133120
#define EB      128                       // evals per block in fused kernel
#define X1_STRIDE 132
#define PART    (2048 * H1)               // offset of k-partial #1 in each scratch array

typedef unsigned long long u64;

// packed fp32x2 fma: d = a*b + d (lane-wise). PTX-only route to SASS FFMA2.
__device__ __forceinline__ void ffma2(u64& d, u64 a, u64 b) {
    asm("fma.rn.f32x2 %0, %1, %2, %0;" : "+l"(d) : "l"(a), "l"(b));
}
__device__ __forceinline__ float pairsum(u64 v) {
    float lo, hi;
    asm("mov.b64 {%0, %1}, %2;" : "=f"(lo), "=f"(hi) : "l"(v));
    return lo + hi;
}
__device__ __forceinline__ u64 packf2(float lo, float hi) {
    u64 v;
    asm("mov.b64 %0, {%1, %2};" : "=l"(v) : "f"(lo), "f"(hi));
    return v;
}

// Scratch (device globals — no allocation allowed). Each array holds two
// k-partials at uniform stride PART (rows padded to 2048 for Ptop/Pbot).
__device__ float g_Ptop[2 * PART];
__device__ float g_Pbot[2 * PART];
__device__ float g_Tbot[2 * PART];

// ---------------------------------------------------------------------------
// Kernel 1: projection GEMMs, split-K=2, packed-f32x2 inner product.
// grid (64, 3, 2): y = segment (0 Ptop, 1 Pbot, 2 Tbot via t-gather), z = k-half.
// BM=32, BN=128, BK=32, 256 threads. Thread (ty=warp, tx=lane): rows 4ty+r,
// cols tx+32g. B staged k-pair-interleaved Bs[kp*256 + 2c + (k&1)]:
//   reads: LDS.64 @ 2tx+64g -> 2-way (optimal); A reads warp-uniform broadcast.
//   staging: coalesced LDG.32 + stride-2 STS.64 (2-way).
// acc2[r][g] = f32x2 (even-k sum, odd-k sum); final = lo+hi.
// ---------------------------------------------------------------------------
__global__ __launch_bounds__(256) void proj_kernel(const float* __restrict__ embed,
                                                   const float* __restrict__ W1,
                                                   const int* __restrict__ t) {
    const int seg  = blockIdx.y;
    const int kz   = blockIdx.z;
    const int rows = (seg == 2) ? BB : DRUG;
    const int row0 = blockIdx.x * 32;
    if (row0 >= rows) return;
    const int woff = (seg == 0) ? 0 : D;
    float* dst = ((seg == 0) ? g_Ptop : (seg == 1) ? g_Pbot : g_Tbot) + kz * PART;

    __shared__ float As[32][32];
    __shared__ float Bs[16 * 256];      // k-pair interleaved

    const int tid = threadIdx.x;

    const int ar = tid >> 3;            // row in tile (0..31)
    const int ac = (tid & 7) << 2;      // k offset
    const int arow = row0 + ar;
    int srow = (arow < rows) ? arow : (rows - 1);
    if (seg == 2) srow = t[srow];       // gather tail row via t index
    const float* src = embed + (long)srow * D;

    const int ty = tid >> 5;            // warp 0..7 -> rows 4ty..4ty+3
    const int tx = tid & 31;            // cols tx + 32g

    u64 acc2[4][4];
#pragma unroll
    for (int r = 0; r < 4; r++)
#pragma unroll
        for (int g = 0; g < 4; g++) acc2[r][g] = 0ULL;

    const int kbeg = kz * 256;
    for (int k0 = kbeg; k0 < kbeg + 256; k0 += 32) {
        // A tile [32 rows x 32 k]
        float4 av = *(const float4*)(src + k0 + ac);
        *(float4*)&As[ar][ac] = av;
        // B tile staged k-pair-interleaved: unit u = (kp, c0)
#pragma unroll
        for (int j = 0; j < 2; j++) {
            int u  = tid + j * 256;      // 0..511
            int kp = u >> 5;             // 0..15
            int c0 = u & 31;             // lane-consecutive col base
            const float* w0 = W1 + (long)(woff + k0 + 2 * kp) * H1;
            const float* w1 = w0 + H1;
#pragma unroll
            for (int g = 0; g < 4; g++) {
                int c = c0 + 32 * g;
                *(u64*)&Bs[kp * 256 + 2 * c] = packf2(w0[c], w1[c]);
            }
        }
        __syncthreads();
#pragma unroll
        for (int kp = 0; kp < 16; kp++) {
            u64 bp[4];
#pragma unroll
            for (int g = 0; g < 4; g++)
                bp[g] = *(const u64*)&Bs[kp * 256 + 2 * (tx + 32 * g)];
#pragma unroll
            for (int r = 0; r < 4; r++) {
                u64 a = *(const u64*)&As[ty * 4 + r][kp * 2];  // warp-uniform
#pragma unroll
                for (int g = 0; g < 4; g++)
                    ffma2(acc2[r][g], a, bp[g]);
            }
        }
        __syncthreads();
    }

#pragma unroll
    for (int r = 0; r < 4; r++) {
        int row = row0 + ty * 4 + r;
        if (row < rows) {
#pragma unroll
            for (int g = 0; g < 4; g++)
                dst[row * H1 + tx + 32 * g] = pairsum(acc2[r][g]);
        }
    }
}

// ---------------------------------------------------------------------------
// Kernel 2: fused layers 1..3 (byte-identical to the measured 66.0us version).
// 128 evals/block, 256 threads, 4x8 microtile, stage-1 sums both k-partials.
// ---------------------------------------------------------------------------
__global__ __launch_bounds__(256, 2) void mlp_kernel(const float* __restrict__ b1,
                                                     const float* __restrict__ W2,
                                                     const float* __restrict__ b2,
                                                     const float* __restrict__ W3,
                                                     const float* __restrict__ b3,
                                                     const int* __restrict__ h,
                                                     const int* __restrict__ ns,
                                                     float* __restrict__ out) {
    extern __shared__ float sm[];
    float* W2p = sm;                     // 64 k-pairs * 128 floats = 8192
    float* X1  = sm + H1 * H2;           // 128 * 132 floats

    __shared__ float b1s[H1];
    __shared__ float b2s[H2];
    __shared__ float W3s[H2];
    __shared__ const float* headp[EB];
    __shared__ const float* tailp[EB];
    __shared__ int outoff[EB];

    const int tid = threadIdx.x;
    const int e0 = blockIdx.x * EB;

    // -------- pointer / output-offset setup (first 128 threads) ------------
    if (tid < EB) {
        int e = e0 + tid;
        int b = e / EVALS_PER_B;
        int s = e - b * EVALS_PER_B;
        int hidx, ooff;
        const float* tp;
        if (s == 0) {
            hidx = h[b];
            tp = g_Tbot + b * H1;
            ooff = b;
        } else {
            int nsv = ns[b * 64 + (s - 1)];
            if (s <= 32) {
                hidx = h[b];
                tp = g_Pbot + nsv * H1;
            } else {
                hidx = nsv;
                tp = g_Tbot + b * H1;
            }
            ooff = BB + b * 64 + (s - 1);
        }
        headp[tid] = g_Ptop + hidx * H1;
        tailp[tid] = tp;
        outoff[tid] = ooff;
    }
    if (tid < H1) b1s[tid] = b1[tid];
    if (tid >= 128 && tid < 128 + H2) b2s[tid - 128] = b2[tid - 128];
    if (tid >= 192 && tid < 192 + H2) W3s[tid - 192] = W3[tid - 192];
    // W2 -> k-pair-interleaved smem
#pragma unroll
    for (int i = 0; i < 8; i++) {        // 2048 float4 / 256 threads
        int f4 = tid + i * 256;
        int k  = f4 >> 4;                // W2 row (16 float4 per 64-wide row)
        int c4 = (f4 & 15) << 2;         // starting col
        float4 v = *(const float4*)&W2[k * H2 + c4];
        float* dstp = &W2p[((k >> 1) << 7) + (k & 1)];
        dstp[(c4 + 0) * 2] = v.x;
        dstp[(c4 + 1) * 2] = v.y;
        dstp[(c4 + 2) * 2] = v.z;
        dstp[(c4 + 3) * 2] = v.w;
    }
    __syncthreads();

    // -------- Stage 1: X1 [128][128], summing both k-partials ---------------
#pragma unroll
    for (int i = 0; i < 16; i++) {
        int idx4 = tid + i * 256;        // 0..4095 float4s
        int e = idx4 >> 5;               // warp-uniform
        int c = (idx4 & 31) << 2;
        const float* hp = headp[e] + c;
        const float* tp = tailp[e] + c;
        float4 h0 = *(const float4*)hp;
        float4 h1 = *(const float4*)(hp + PART);
        float4 t0 = *(const float4*)tp;
        float4 t1 = *(const float4*)(tp + PART);
        float4 bv = *(const float4*)&b1s[c];
        float4 xv;
        xv.x = fmaxf(h0.x + h1.x + t0.x + t1.x + bv.x, 0.f);
        xv.y = fmaxf(h0.y + h1.y + t0.y + t1.y + bv.y, 0.f);
        xv.z = fmaxf(h0.z + h1.z + t0.z + t1.z + bv.z, 0.f);
        xv.w = fmaxf(h0.w + h1.w + t0.w + t1.w + bv.w, 0.f);
        *(float4*)&X1[e * X1_STRIDE + c] = xv;
    }
    __syncthreads();

    // -------- Stage 2: 4x8 microtile GEMM in packed f32x2 ------------------
    const int ty = tid >> 3;             // 0..31, rows ty + 32r
    const int tx = tid & 7;              // 0..7
    u64 acc2[4][8];
#pragma unroll
    for (int r = 0; r < 4; r++)
#pragma unroll
        for (int c = 0; c < 8; c++) acc2[r][c] = 0ULL;

    for (int k0 = 0; k0 < H1; k0 += 4) {
        ulonglong2 av[4];                // .x = X1[k0,k0+1], .y = X1[k0+2,k0+3]
#pragma unroll
        for (int r = 0; r < 4; r++)
            av[r] = *(const ulonglong2*)&X1[(ty + 32 * r) * X1_STRIDE + k0];
#pragma unroll
        for (int p = 0; p < 2; p++) {    // k-pair (k0+2p, k0+2p+1)
            const float* wrow = &W2p[(((k0 >> 1) + p) << 7)];
            ulonglong2 wv[4];
#pragma unroll
            for (int g = 0; g < 4; g++)  // cols {16g+2tx, 16g+2tx+1}
                wv[g] = *(const ulonglong2*)&wrow[32 * g + (tx << 2)];
#pragma unroll
            for (int r = 0; r < 4; r++) {
                u64 a = p ? av[r].y : av[r].x;
#pragma unroll
                for (int g = 0; g < 4; g++) {
                    ffma2(acc2[r][2 * g + 0], a, wv[g].x);
                    ffma2(acc2[r][2 * g + 1], a, wv[g].y);
                }
            }
        }
    }

    // -------- Stage 3: out = relu(acc + b2) . W3 + b3 ----------------------
    const float b3v = b3[0];
#pragma unroll
    for (int r = 0; r < 4; r++) {
        float p = 0.f;
#pragma unroll
        for (int g = 0; g < 4; g++)
#pragma unroll
            for (int i = 0; i < 2; i++) {
                int c = 16 * g + 2 * tx + i;
                float a = pairsum(acc2[r][2 * g + i]);
                p += fmaxf(a + b2s[c], 0.f) * W3s[c];
            }
        p += __shfl_xor_sync(0xffffffffu, p, 4, 8);
        p += __shfl_xor_sync(0xffffffffu, p, 2, 8);
        p += __shfl_xor_sync(0xffffffffu, p, 1, 8);
        if (tx == 0) out[outoff[ty + 32 * r]] = p + b3v;
    }
}

// ---------------------------------------------------------------------------
extern "C" void kernel_launch(void* const* d_in, const int* in_sizes, int n_in,
                              void* d_out, int out_size) {
    const float* embed = (const float*)d_in[0];
    const float* W1    = (const float*)d_in[1];
    const float* b1    = (const float*)d_in[2];
    const float* W2    = (const float*)d_in[3];
    const float* b2    = (const float*)d_in[4];
    const float* W3    = (const float*)d_in[5];
    const float* b3    = (const float*)d_in[6];
    const int*   h     = (const int*)d_in[7];
    const int*   t     = (const int*)d_in[8];
    const int*   ns    = (const int*)d_in[9];
    float* out = (float*)d_out;

    // Idempotent, not a stream op (invisible to graph capture), no static guard.
    const int dyn_smem = (H1 * H2 + EB * X1_STRIDE) * (int)sizeof(float); // 100352 B
    cudaFuncSetAttribute(mlp_kernel, cudaFuncAttributeMaxDynamicSharedMemorySize, dyn_smem);

    dim3 g1(64, 3, 2);  // 64 row-tiles x 3 segments x 2 k-halves
    proj_kernel<<<g1, 256>>>(embed, W1, t);

    mlp_kernel<<<TOTAL_EVALS / EB, 256, dyn_smem>>>(b1, W2, b2, W3, b3, h, ns, out);
}